// round 9
// baseline (speedup 1.0000x reference)
#include <cuda_runtime.h>
#include <math.h>

#define NH    200
#define BR    8
#define IND   120
#define OD    35
#define TT    250
#define PER   15
#define BPC   4
#define NTHR  1024
#define W2SU  201        // W2dup row stride (u64)
#define NSL   6          // readout slices
#define SLW   34         // neurons per slice (last = 30)

typedef unsigned long long u64;

__device__ __forceinline__ u64 pk2(float lo, float hi) {
    u64 r; asm("mov.b64 %0,{%1,%2};" : "=l"(r) : "f"(lo), "f"(hi)); return r;
}
__device__ __forceinline__ void upk2(u64 v, float& lo, float& hi) {
    asm("mov.b64 {%0,%1},%2;" : "=f"(lo), "=f"(hi) : "l"(v));
}
__device__ __forceinline__ u64 fma2(u64 a, u64 b, u64 c) {
    u64 d; asm("fma.rn.f32x2 %0,%1,%2,%3;" : "=l"(d) : "l"(a), "l"(b), "l"(c)); return d;
}
__device__ __forceinline__ u64 mul2(u64 a, u64 b) {
    u64 d; asm("mul.rn.f32x2 %0,%1,%2;" : "=l"(d) : "l"(a), "l"(b)); return d;
}
__device__ __forceinline__ u64 add2(u64 a, u64 b) {
    u64 d; asm("add.rn.f32x2 %0,%1,%2;" : "=l"(d) : "l"(a), "l"(b)); return d;
}
__device__ __forceinline__ float sigm(float v) { return 1.0f / (1.0f + expf(-v)); }

// ---- dynamic smem layout (bytes) ----
#define OFF_W1   0                         // u64 [64 slots][200*2-lane] = 102400
#define OFF_W2   102400                    // u64 [35][201] = 56280 -> 56288
#define OFF_XS   (OFF_W2 + 56288)          // float [2][4][128] = 4096
#define OFF_LP   (OFF_XS + 4096)           // u64 [2][4][200] = 12800
#define OFF_SPK  (OFF_LP + 12800)          // u64 [2][200][2] = 6400
#define OFF_PS   (OFF_SPK + 6400)          // u64 [2][2][210] = 6720
#define OFF_ACC  (OFF_PS + 6720)           // float [4][35] -> 576
#define SMEM_TOTAL (OFF_ACC + 576)         // ~189.3 KB

__global__ __launch_bounds__(NTHR, 1)
void snn_r8_kernel(const float* __restrict__ x,
                   const float* __restrict__ W1,
                   const float* __restrict__ b1,
                   const float* __restrict__ tau_m1,
                   const float* __restrict__ tau_n1,
                   const float* __restrict__ W2,
                   const float* __restrict__ b2,
                   const float* __restrict__ tau_m2,
                   float* __restrict__ out)
{
    extern __shared__ __align__(16) char smem[];
    u64  *w1u   = (u64*)(smem + OFF_W1);   // [(k*4+mp)*400 + 2n + {0,1}] pair-contiguous
    u64  *w2d   = (u64*)(smem + OFF_W2);   // [o*201 + n], lanes duplicated
    float (*xs)[BPC][128] = (float (*)[BPC][128])(smem + OFF_XS);
    u64  *lpB   = (u64*)(smem + OFF_LP);   // [buf*800 + j*200 + n], j = half*2+hb
    u64  *spkB  = (u64*)(smem + OFF_SPK);  // [buf*400 + n*2 + pair]
    u64  *psB   = (u64*)(smem + OFF_PS);   // [buf*420 + pair*210 + r]
    float (*accS)[OD] = (float (*)[OD])(smem + OFF_ACC);

    const int tid = threadIdx.x;
    const int b0  = blockIdx.x * BPC;

    // ---- roles ----
    const bool isDen = (tid < 800);
    const int  hb   = tid / 400;          // branch half (branches hb*4 .. hb*4+3)
    const int  rem  = tid - hb * 400;
    const int  half = rem / 200;          // batch pair {2*half, 2*half+1}
    const int  dn   = rem - half * 200;   // neuron

    const int  sx    = tid - 800;
    const bool doSom = (sx >= 0 && sx < NH);         // 800..999, neuron sx
    const bool doRO  = (sx >= 0 && sx < NSL * OD);   // 800..1009
    const int  ss    = doRO ? (sx / OD) : 0;
    const int  oo    = doRO ? (sx - ss * OD) : 0;
    const int  rn0   = ss * SLW;
    const int  rn1   = (rn0 + SLW < NH) ? (rn0 + SLW) : NH;
    const int  rd    = tid - 989;                    // reduce threads 989..1023
    const bool doRED = (rd >= 0 && rd < OD);

    // ---- init W1: fold (1-beta), pair-pack, pair-contiguous slot-major ----
    for (int i = tid; i < NH * BR; i += NTHR) {
        int nn = i >> 3, k = i & 7;
        float bt = sigm(tau_n1[nn * BR + k]);
        float sc = 1.0f - bt;
        const float* src = W1 + (size_t)nn * (BR * IND) + k * IND + k * PER;
        float wr[16];
        #pragma unroll
        for (int j = 0; j < PER; j++) wr[j] = src[j] * sc;
        wr[15] = 0.0f;
        #pragma unroll
        for (int m = 0; m < 8; m++)
            w1u[(k * 4 + (m >> 1)) * 400 + nn * 2 + (m & 1)] = pk2(wr[2*m], wr[2*m+1]);
    }
    // ---- init W2 duplicated ----
    for (int i = tid; i < OD * NH; i += NTHR) {
        int o = i / NH, nn = i - o * NH;
        float wv = W2[i];
        w2d[o * W2SU + nn] = pk2(wv, wv);
    }
    // zero slot-15 pads of xs
    if (tid < 64) {
        int buf = tid >> 5, rr2 = tid & 31, bj = rr2 >> 3, k = rr2 & 7;
        xs[buf][bj][k * 16 + 15] = 0.0f;
    }

    // ---- dendrite persistent state ----
    float beta[4], dstA[4], dstB[4];
    if (isDen) {
        #pragma unroll
        for (int kk = 0; kk < 4; kk++)
            beta[kk] = sigm(tau_n1[dn * BR + hb * 4 + kk]);
    }
    #pragma unroll
    for (int kk = 0; kk < 4; kk++) { dstA[kk] = 0.f; dstB[kk] = 0.f; }

    // ---- soma state (threads 800..999, neuron sx) ----
    float a1 = 0.f, oma1 = 0.f, bb1 = 0.f;
    float m1[BPC], sp1[BPC];
    #pragma unroll
    for (int bj = 0; bj < BPC; bj++) { m1[bj] = 0.f; sp1[bj] = 0.f; }
    if (doSom) { a1 = sigm(tau_m1[sx]); oma1 = 1.0f - a1; bb1 = b1[sx]; }

    // ---- integrator state (threads 989..1023) ----
    float a2 = 0.f, bb2 = 0.f, mem2[BPC], racc[BPC];
    #pragma unroll
    for (int bj = 0; bj < BPC; bj++) { mem2[bj] = 0.f; racc[bj] = 0.f; }
    if (doRED) { a2 = sigm(tau_m2[rd]); bb2 = b2[rd]; }

    // ---- x loader: threads 0..479, one (batch, feature) each ----
    const bool isLd = (tid < BPC * IND);
    const float* xptr = nullptr;
    int lbj = 0, xoff = 0;
    if (isLd) {
        lbj = tid / IND;
        int f = tid - lbj * IND;
        int c = f / 40, dd = f - c * 40;
        xptr = x + ((size_t)((b0 + lbj) * 3 + c) * TT) * 40 + dd;
        xoff = (f / PER) * 16 + (f % PER);
    }
    if (isLd) xs[0][lbj][xoff] = xptr[0];
    __syncthreads();

    const int bA = 2 * half, bB = bA + 1;

    // ======== main loop: 5-stage pipeline, 1 barrier/iteration ========
    for (int t = 0; t < TT + 3; t++) {
        const int cur = t & 1, prv = cur ^ 1;

        float xn = 0.0f;
        if (isLd && t < TT - 1) xn = __ldg(xptr + (size_t)(t + 1) * 40);

        // ---- stage 1: dendrite quarter for step t (threads 0..799) ----
        if (t < TT && isDen) {
            float accA = 0.f, accB = 0.f;
            #pragma unroll
            for (int kk = 0; kk < 4; kk++) {
                const int k = hb * 4 + kk;
                const ulonglong2* wv = (const ulonglong2*)w1u + k * 800 + dn;
                ulonglong2 W0 = wv[0];
                ulonglong2 W1v = wv[200];
                ulonglong2 W2v = wv[400];
                ulonglong2 W3v = wv[600];

                const ulonglong2* xa = (const ulonglong2*)xs[cur][bA] + k * 4;
                ulonglong2 A0 = xa[0], A1 = xa[1], A2 = xa[2], A3 = xa[3];
                u64 sA = mul2(A0.x, W0.x);
                u64 sB = mul2(A0.y, W0.y);
                sA = fma2(A1.x, W1v.x, sA);
                sB = fma2(A1.y, W1v.y, sB);
                sA = fma2(A2.x, W2v.x, sA);
                sB = fma2(A2.y, W2v.y, sB);
                sA = fma2(A3.x, W3v.x, sA);
                sB = fma2(A3.y, W3v.y, sB);
                float il, ih; upk2(add2(sA, sB), il, ih);
                float da = fmaf(beta[kk], dstA[kk], il + ih);
                dstA[kk] = da; accA += da;

                const ulonglong2* xb = (const ulonglong2*)xs[cur][bB] + k * 4;
                ulonglong2 B0 = xb[0], B1 = xb[1], B2 = xb[2], B3 = xb[3];
                u64 tA = mul2(B0.x, W0.x);
                u64 tB = mul2(B0.y, W0.y);
                tA = fma2(B1.x, W1v.x, tA);
                tB = fma2(B1.y, W1v.y, tB);
                tA = fma2(B2.x, W2v.x, tA);
                tB = fma2(B2.y, W2v.y, tB);
                tA = fma2(B3.x, W3v.x, tA);
                tB = fma2(B3.y, W3v.y, tB);
                float jl, jh; upk2(add2(tA, tB), jl, jh);
                float db = fmaf(beta[kk], dstB[kk], jl + jh);
                dstB[kk] = db; accB += db;
            }
            lpB[cur * 800 + (half * 2 + hb) * 200 + dn] = pk2(accA, accB);
        }

        // stage next x into the other buffer
        if (isLd && t < TT - 1) xs[prv][lbj][xoff] = xn;

        // ---- stage 2: soma for step t-1 (threads 800..999) ----
        if (doSom && t >= 1 && t <= TT) {
            const u64* lpp = lpB + prv * 800;
            u64 l01 = add2(lpp[0 * 200 + sx], lpp[1 * 200 + sx]);   // batches 0,1
            u64 l23 = add2(lpp[2 * 200 + sx], lpp[3 * 200 + sx]);   // batches 2,3
            float l0, l1, l2, l3;
            upk2(l01, l0, l1); upk2(l23, l2, l3);
            l0 += bb1; l1 += bb1; l2 += bb1; l3 += bb1;
            float v0 = fmaf(a1, m1[0] - sp1[0], oma1 * l0);
            m1[0] = v0; sp1[0] = (v0 > 1.0f) ? 1.0f : 0.0f;
            float v1 = fmaf(a1, m1[1] - sp1[1], oma1 * l1);
            m1[1] = v1; sp1[1] = (v1 > 1.0f) ? 1.0f : 0.0f;
            float v2 = fmaf(a1, m1[2] - sp1[2], oma1 * l2);
            m1[2] = v2; sp1[2] = (v2 > 1.0f) ? 1.0f : 0.0f;
            float v3 = fmaf(a1, m1[3] - sp1[3], oma1 * l3);
            m1[3] = v3; sp1[3] = (v3 > 1.0f) ? 1.0f : 0.0f;
            ulonglong2 st;
            st.x = pk2(sp1[0], sp1[1]);
            st.y = pk2(sp1[2], sp1[3]);
            ((ulonglong2*)(spkB + cur * 400))[sx] = st;
        }

        // ---- stage 3: readout partials for step t-2 (threads 800..1009) ----
        if (doRO && t >= 2 && t <= TT + 1) {
            const ulonglong2* sp2 = (const ulonglong2*)(spkB + prv * 400);
            const u64* wrow = w2d + oo * W2SU;
            u64 q0a = 0, q0b = 0, q1a = 0, q1b = 0;
            int nn = rn0;
            for (; nn + 2 <= rn1; nn += 2) {
                ulonglong2 sa = sp2[nn];
                u64 wa = wrow[nn];
                q0a = fma2(sa.x, wa, q0a);
                q1a = fma2(sa.y, wa, q1a);
                ulonglong2 sb = sp2[nn + 1];
                u64 wb = wrow[nn + 1];
                q0b = fma2(sb.x, wb, q0b);
                q1b = fma2(sb.y, wb, q1b);
            }
            psB[cur * 420 + 0 * 210 + sx] = add2(q0a, q0b);
            psB[cur * 420 + 1 * 210 + sx] = add2(q1a, q1b);
        }

        // ---- stage 4: reduce + integrator for step t-3 (threads 989..1023) ----
        if (doRED && t >= 3) {
            const u64* pp = psB + prv * 420;
            u64 s0 = pp[rd];
            u64 s1 = pp[210 + rd];
            #pragma unroll
            for (int s2 = 1; s2 < NSL; s2++) {
                s0 = add2(s0, pp[s2 * OD + rd]);
                s1 = add2(s1, pp[210 + s2 * OD + rd]);
            }
            float r0, r1, r2, r3;
            upk2(s0, r0, r1); upk2(s1, r2, r3);
            float t0 = r0 + bb2, t1 = r1 + bb2, t2 = r2 + bb2, t3 = r3 + bb2;
            float w0 = fmaf(a2, mem2[0] - t0, t0); mem2[0] = w0; racc[0] += w0;
            float w1v = fmaf(a2, mem2[1] - t1, t1); mem2[1] = w1v; racc[1] += w1v;
            float w2v = fmaf(a2, mem2[2] - t2, t2); mem2[2] = w2v; racc[2] += w2v;
            float w3v = fmaf(a2, mem2[3] - t3, t3); mem2[3] = w3v; racc[3] += w3v;
        }

        __syncthreads();
    }

    // ---- epilogue: log_softmax(acc/T) per batch ----
    if (doRED) {
        #pragma unroll
        for (int bj = 0; bj < BPC; bj++)
            accS[bj][rd] = racc[bj] * (1.0f / TT);
    }
    __syncthreads();
    if (sx >= 0 && sx < BPC * OD) {   // threads 800..939
        int bj = sx / OD, o = sx - bj * OD;
        float m = -INFINITY;
        #pragma unroll
        for (int i = 0; i < OD; i++) m = fmaxf(m, accS[bj][i]);
        float se = 0.0f;
        #pragma unroll
        for (int i = 0; i < OD; i++) se += expf(accS[bj][i] - m);
        out[(size_t)(b0 + bj) * OD + o] = accS[bj][o] - m - logf(se);
    }
}

extern "C" void kernel_launch(void* const* d_in, const int* in_sizes, int n_in,
                              void* d_out, int out_size)
{
    const float* x      = (const float*)d_in[0];
    const float* W1     = (const float*)d_in[1];
    const float* b1     = (const float*)d_in[2];
    const float* tau_m1 = (const float*)d_in[3];
    const float* tau_n1 = (const float*)d_in[4];
    const float* W2     = (const float*)d_in[5];
    const float* b2     = (const float*)d_in[6];
    const float* tau_m2 = (const float*)d_in[7];
    float* out = (float*)d_out;

    cudaFuncSetAttribute(snn_r8_kernel,
                         cudaFuncAttributeMaxDynamicSharedMemorySize, SMEM_TOTAL);

    const int B = in_sizes[0] / (3 * TT * 40);   // 512
    snn_r8_kernel<<<B / BPC, NTHR, SMEM_TOTAL>>>(x, W1, b1, tau_m1, tau_n1,
                                                 W2, b2, tau_m2, out);
}